// round 16
// baseline (speedup 1.0000x reference)
#include <cuda_runtime.h>
#include <cstdint>

// MinimalRSNN: GLIF3 + AlphaPSC recurrent SNN.
//   Phase A: I_ext = x @ W_in^T  (fp32 SGEMM, pipelined, f32x2 FMA)
//   Phase B: persistent 1000-step scan, 256 CTAs x 128 thr, 2 CTAs/SM
//            spikes exchanged as BIT MASKS (4KB/step, 4-buffer ring):
//            ballot + red.or write; coalesced u32 read + smem LUT -> exact
//            f32x2 0/1 pairs; FMA order bit-identical to R15.
//   Phase C: out = spike_rate @ W_out^T

#define T_STEPS 1000
#define BATCH   32
#define NI      512
#define NH      1024
#define NO      256

#define V_TH   (-45.0f)
#define V_RST  (-60.0f)
#define D_SYN  0.8187307530779818f
#define D_A0   0.9048374180359595f
#define D_A1   0.8187307530779818f

#define NBLK   256      // scan CTAs (2 per SM)

#define FMA2(d, a, b)  asm("fma.rn.f32x2 %0, %1, %2, %0;" : "+l"(d) : "l"(a), "l"(b))
#define PACK2(d, lo, hi) asm("mov.b64 %0, {%1, %2};" : "=l"(d) : "r"(lo), "r"(hi))
#define UNPK2(lo, hi, s) asm("mov.b64 {%0, %1}, %2;" : "=r"(lo), "=r"(hi) : "l"(s))

typedef unsigned long long u64;
typedef unsigned int       u32;

// -------- device scratch (no allocations allowed) --------
__device__ float        g_Iext[(size_t)T_STEPS * BATCH * NH];   // 131 MB
__device__ u32          g_spkb[4][BATCH * 32];                  // bit spikes, 4-ring
__device__ float        g_rate[BATCH * NH];
__device__ unsigned int g_bar;

__global__ void init_kernel() {
    if (threadIdx.x == 0) g_bar = 0u;
    for (int i = threadIdx.x; i < 4 * BATCH * 32; i += blockDim.x)
        ((u32*)g_spkb)[i] = 0u;
}

// -------- Phase A: C[M,N] = A[M,K] * B[N,K]^T (pipelined fp32) --------
#define BM 128
#define BN 128
#define BK 8
#define NCHUNK (NI / BK)
__global__ __launch_bounds__(256, 2) void gemm_in_kernel(const float* __restrict__ A,
                                                         const float* __restrict__ Bm) {
    __shared__ float As[2][BK][BM];
    __shared__ float Bs[2][BK][BN];
    const int tid = threadIdx.x;
    const int m0 = blockIdx.y * BM, n0 = blockIdx.x * BN;
    const int lr = tid >> 1;
    const int lc = (tid & 1) * 4;
    const int tx = tid & 15, ty = tid >> 4;
    u64 acc[8][4];
#pragma unroll
    for (int i = 0; i < 8; i++)
#pragma unroll
        for (int j = 0; j < 4; j++) acc[i][j] = 0ull;

    {
        float4 av = *(const float4*)&A [(size_t)(m0 + lr) * NI + lc];
        float4 bv = *(const float4*)&Bm[(size_t)(n0 + lr) * NI + lc];
        As[0][lc + 0][lr] = av.x; As[0][lc + 1][lr] = av.y;
        As[0][lc + 2][lr] = av.z; As[0][lc + 3][lr] = av.w;
        Bs[0][lc + 0][lr] = bv.x; Bs[0][lc + 1][lr] = bv.y;
        Bs[0][lc + 2][lr] = bv.z; Bs[0][lc + 3][lr] = bv.w;
    }
    __syncthreads();

    for (int kc = 0; kc < NCHUNK; kc++) {
        const int buf = kc & 1;
        float4 avn, bvn;
        if (kc + 1 < NCHUNK) {
            avn = *(const float4*)&A [(size_t)(m0 + lr) * NI + (kc + 1) * BK + lc];
            bvn = *(const float4*)&Bm[(size_t)(n0 + lr) * NI + (kc + 1) * BK + lc];
        }
#pragma unroll
        for (int k = 0; k < BK; k++) {
            float4 a0 = *(const float4*)&As[buf][k][ty * 8];
            float4 a1 = *(const float4*)&As[buf][k][ty * 8 + 4];
            ulonglong2 bp = *(const ulonglong2*)&Bs[buf][k][tx * 8];
            ulonglong2 bq = *(const ulonglong2*)&Bs[buf][k][tx * 8 + 4];
            float aa[8] = {a0.x, a0.y, a0.z, a0.w, a1.x, a1.y, a1.z, a1.w};
            u64 ap[8];
#pragma unroll
            for (int i = 0; i < 8; i++) {
                u32 ab = __float_as_uint(aa[i]);
                PACK2(ap[i], ab, ab);
            }
#pragma unroll
            for (int i = 0; i < 8; i++) {
                FMA2(acc[i][0], ap[i], bp.x);
                FMA2(acc[i][1], ap[i], bp.y);
                FMA2(acc[i][2], ap[i], bq.x);
                FMA2(acc[i][3], ap[i], bq.y);
            }
        }
        if (kc + 1 < NCHUNK) {
            const int nb = buf ^ 1;
            As[nb][lc + 0][lr] = avn.x; As[nb][lc + 1][lr] = avn.y;
            As[nb][lc + 2][lr] = avn.z; As[nb][lc + 3][lr] = avn.w;
            Bs[nb][lc + 0][lr] = bvn.x; Bs[nb][lc + 1][lr] = bvn.y;
            Bs[nb][lc + 2][lr] = bvn.z; Bs[nb][lc + 3][lr] = bvn.w;
            __syncthreads();
        }
    }
#pragma unroll
    for (int i = 0; i < 8; i++) {
        float o[8];
#pragma unroll
        for (int j = 0; j < 4; j++) {
            u32 lo, hi;
            UNPK2(lo, hi, acc[i][j]);
            o[2 * j]     = __uint_as_float(lo);
            o[2 * j + 1] = __uint_as_float(hi);
        }
        float4 o0 = {o[0], o[1], o[2], o[3]};
        float4 o1 = {o[4], o[5], o[6], o[7]};
        float* dst = &g_Iext[(size_t)(m0 + ty * 8 + i) * NH + n0 + tx * 8];
        *(float4*)dst = o0;
        *(float4*)(dst + 4) = o1;
    }
}

// -------- grid barrier: release arrive, acquire poll --------
__device__ __forceinline__ void grid_sync(int step) {
    __syncthreads();
    if (threadIdx.x == 0) {
        asm volatile("red.release.gpu.global.add.u32 [%0], 1;"
                     :: "l"(&g_bar) : "memory");
        const unsigned target = (unsigned)(step + 1) * NBLK;
        unsigned cur;
        do {
            asm volatile("ld.global.acquire.gpu.u32 %0, [%1];" : "=r"(cur) : "l"(&g_bar));
        } while (cur < target);
    }
    __syncthreads();
}

#define RSTAGE(M, NHALF)                                                        \
    if (ln & (M)) {                                                             \
        _Pragma("unroll")                                                       \
        for (int i = 0; i < (NHALF); i++) {                                     \
            float tmp = a[i]; a[i] = a[i + (NHALF)]; a[i + (NHALF)] = tmp;      \
        }                                                                       \
    }                                                                           \
    _Pragma("unroll")                                                           \
    for (int i = 0; i < (NHALF); i++)                                           \
        a[i] += __shfl_xor_sync(0xffffffffu, a[i + (NHALF)], (M));

// -------- Phase B: persistent scan, bit-packed spikes --------
// CTA c owns h in [4c,4c+4); warp w owns batches [8w,8w+8).
// Spike word layout: row b, word W, bits 4r..4r+3 = nibble of CTA
// c = 8*(W&3) + r + 32*(W>>2)   (inverse: c -> W=((c>>3)&3)+4*(c>>5), r=c&7).
// Reader (lane ln, u) needs c = ln+32u -> W=(ln>>3)+4u, r=ln&7.  Verified.
__global__ __launch_bounds__(128, 2) void scan_kernel(const float* __restrict__ Wrec) {
    __shared__ float       wt[4 * NH];      // 16 KB weights
    __shared__ u32         stg[4 * 256];    // 4 KB spike words (per warp 256)
    __shared__ ulonglong2  lut[16];         // nibble -> two f32x2 0/1 pairs

    const int tid = threadIdx.x;
    const int w  = tid >> 5;
    const int ln = tid & 31;
    const int c  = blockIdx.x;
    const int h0 = c * 4;

    {
        const float4* src = (const float4*)(Wrec + (size_t)h0 * NH);
#pragma unroll
        for (int i = 0; i < 8; i++)
            ((float4*)wt)[tid + i * 128] = src[tid + i * 128];
    }
    if (tid < 16) {
        const u32 f = 0x3F800000u;
        u64 lo = ((u64)((tid & 2) ? f : 0u) << 32) | ((tid & 1) ? f : 0u);
        u64 hi = ((u64)((tid & 8) ? f : 0u) << 32) | ((tid & 4) ? f : 0u);
        ulonglong2 e; e.x = lo; e.y = hi;
        lut[tid] = e;
    }
    __syncthreads();

    const int b  = 8 * w + (ln >> 2);
    const int h  = h0 + (ln & 3);
    const int Wc = ((c >> 3) & 3) + 4 * (c >> 5);
    const int rc = c & 7;
    const int shamt = (ln & 7) * 4;
    const float* wbase = wt + 4 * ln;
    u32* mystg = stg + w * 256;

    float v = V_RST, a0 = 0.f, a1 = 0.f, ref = 0.f, hs = 0.f, psc = 0.f;
    int cnt = 0;
    float Iv = __ldcg(&g_Iext[(size_t)b * NH + h]);

    for (int t = 0; t < T_STEPS; t++) {
        if (t > 0) {
            const u32* spb = g_spkb[(t - 1) & 3];
            // one coalesced wave: word ln of each of this warp's 8 rows
            u32 sw_[8];
#pragma unroll
            for (int bb = 0; bb < 8; bb++)
                sw_[bb] = __ldcg(&spb[(8 * w + bb) * 32 + ln]);
#pragma unroll
            for (int bb = 0; bb < 8; bb++)
                mystg[bb * 32 + ln] = sw_[bb];
            __syncwarp();

            u64 acc[32];
#pragma unroll
            for (int i = 0; i < 32; i++) acc[i] = 0ull;

#pragma unroll
            for (int u = 0; u < 8; u++) {
                u64 p0[8], p1[8];
#pragma unroll
                for (int bb = 0; bb < 8; bb++) {
                    u32 wd  = mystg[bb * 32 + (ln >> 3) + 4 * u];   // broadcast LDS
                    u32 nib = (wd >> shamt) & 0xFu;
                    ulonglong2 pr = lut[nib];                       // LDS.128
                    p0[bb] = pr.x;
                    p1[bb] = pr.y;
                }
#pragma unroll
                for (int hh = 0; hh < 4; hh++) {
                    ulonglong2 wv = *(const ulonglong2*)(wbase + hh * NH + 128 * u);
#pragma unroll
                    for (int bb = 0; bb < 8; bb++) {
                        FMA2(acc[bb * 4 + hh], p0[bb], wv.x);
                        FMA2(acc[bb * 4 + hh], p1[bb], wv.y);
                    }
                }
            }

            float a[32];
#pragma unroll
            for (int i = 0; i < 32; i++) {
                u32 lo, hi;
                UNPK2(lo, hi, acc[i]);
                a[i] = __uint_as_float(lo) + __uint_as_float(hi);
            }
            RSTAGE(16, 16)
            RSTAGE(8, 8)
            RSTAGE(4, 4)
            RSTAGE(2, 2)
            RSTAGE(1, 1)
            float rec = a[0];

            hs  = D_SYN * hs + rec;
            psc = D_SYN * psc + hs;
        }

        float I = Iv + psc;
        a0 *= D_A0;
        a1 *= D_A1;
        v = v + ((V_RST - v) * (1.0f / 20.0f) + (I + a0 + a1) * 0.5f);
        bool in_ref = ref > 0.0f;
        if (in_ref) v = V_RST;
        float spike = (!in_ref && v >= V_TH) ? 1.0f : 0.0f;
        if (spike > 0.0f) {
            v = V_RST; a0 += 1.0f; a1 -= 2.0f; ref = 2.0f; cnt++;
        } else {
            ref = fmaxf(ref - 1.0f, 0.0f);
        }

        // publish spikes as bits: ballot -> per-row nibble -> red.or
        u32 mask = __ballot_sync(0xffffffffu, spike > 0.0f);
        if (ln < 8) {
            u32 nib = (mask >> (4 * ln)) & 0xFu;
            if (nib) {
                u32* dst = &g_spkb[t & 3][(8 * w + ln) * 32 + Wc];
                asm volatile("red.global.or.b32 [%0], %1;"
                             :: "l"(dst), "r"(nib << (4 * rc)) : "memory");
            }
        }
        // zero the ring buffer that will be written at t+2
        if (tid < 4)
            ((u32*)g_spkb)[((t + 2) & 3) * (BATCH * 32) + c * 4 + tid] = 0u;

        int tn = (t < T_STEPS - 1) ? t + 1 : t;
        Iv = __ldcg(&g_Iext[((size_t)tn * BATCH + b) * NH + h]);

        grid_sync(t);
    }
    g_rate[b * NH + h] = (float)cnt * 0.001f;
}

// -------- Phase C --------
__global__ __launch_bounds__(256) void out_kernel(const float* __restrict__ Wout,
                                                  float* __restrict__ out) {
    int gw   = (blockIdx.x * blockDim.x + threadIdx.x) >> 5;
    int lane = threadIdx.x & 31;
    int b = gw >> 8;
    int o = gw & 255;
    const float* r = &g_rate[b * NH];
    const float* wp = &Wout[(size_t)o * NH];
    float s = 0.f;
    for (int hh = lane; hh < NH; hh += 32) s += r[hh] * wp[hh];
#pragma unroll
    for (int off = 16; off; off >>= 1) s += __shfl_down_sync(0xffffffffu, s, off);
    if (lane == 0) out[b * NO + o] = s;
}

// -------- launch --------
extern "C" void kernel_launch(void* const* d_in, const int* in_sizes, int n_in,
                              void* d_out, int out_size) {
    const float* x = nullptr;
    const float* W_in = nullptr;
    const float* W_rec = nullptr;
    const float* W_out = nullptr;
    for (int i = 0; i < n_in; i++) {
        switch (in_sizes[i]) {
            case T_STEPS * BATCH * NI: x     = (const float*)d_in[i]; break;
            case NH * NI:              W_in  = (const float*)d_in[i]; break;
            case NH * NH:              W_rec = (const float*)d_in[i]; break;
            case NO * NH:              W_out = (const float*)d_in[i]; break;
        }
    }
    float* out = (float*)d_out;

    // harness poisons occupy global idx 0,1
    init_kernel<<<1, 256>>>();                   // global 2

    dim3 g1(NH / BN, (T_STEPS * BATCH) / BM);    // (8, 250)
    gemm_in_kernel<<<g1, 256>>>(x, W_in);        // global 3

    init_kernel<<<1, 256>>>();                   // global 4 (idempotent)

    scan_kernel<<<NBLK, 128>>>(W_rec);           // global 5  <- ncu -s 5 -c 1

    out_kernel<<<(BATCH * NO * 32) / 256, 256>>>(W_out, out);   // global 6
}

// round 17
// speedup vs baseline: 1.1338x; 1.1338x over previous
#include <cuda_runtime.h>
#include <cstdint>

// MinimalRSNN: GLIF3 + AlphaPSC recurrent SNN.
//   Phase A: I_ext = x @ W_in^T  (fp32 SGEMM, pipelined, f32x2 FMA) [R15]
//   Phase B: persistent scan. KEY: batches are independent -> 4 groups of
//            8 batches x 64 CTAs, each group has its OWN barrier (skew over
//            64 CTAs, groups drift freely). CTA = 16h x 8b, weights 64KB in
//            dynamic smem. Per-warp math bit-identical to R15 champion.
//   Phase C: out = spike_rate @ W_out^T

#define T_STEPS 1000
#define BATCH   32
#define NI      512
#define NH      1024
#define NO      256

#define V_TH   (-45.0f)
#define V_RST  (-60.0f)
#define D_SYN  0.8187307530779818f
#define D_A0   0.9048374180359595f
#define D_A1   0.8187307530779818f

#define NBLK   256      // total scan CTAs
#define NGRP   4        // barrier groups (8 batches each)
#define GCTAS  64       // CTAs per group

#define FMA2(d, a, b)  asm("fma.rn.f32x2 %0, %1, %2, %0;" : "+l"(d) : "l"(a), "l"(b))
#define PACK2(d, lo, hi) asm("mov.b64 %0, {%1, %2};" : "=l"(d) : "r"(lo), "r"(hi))
#define UNPK2(lo, hi, s) asm("mov.b64 {%0, %1}, %2;" : "=r"(lo), "=r"(hi) : "l"(s))

typedef unsigned long long u64;
typedef unsigned int       u32;

// -------- device scratch (no allocations allowed) --------
__device__ float        g_Iext[(size_t)T_STEPS * BATCH * NH];   // 131 MB
__device__ float        g_spkf[2][BATCH * NH];                  // float spikes
__device__ float        g_rate[BATCH * NH];
__device__ unsigned int g_bars[NGRP][64];                       // 256B apart

__global__ void init_kernel() {
    if (threadIdx.x < NGRP) g_bars[threadIdx.x][0] = 0u;
}

// -------- Phase A: C[M,N] = A[M,K] * B[N,K]^T (pipelined fp32) --------
#define BM 128
#define BN 128
#define BK 8
#define NCHUNK (NI / BK)
__global__ __launch_bounds__(256, 2) void gemm_in_kernel(const float* __restrict__ A,
                                                         const float* __restrict__ Bm) {
    __shared__ float As[2][BK][BM];
    __shared__ float Bs[2][BK][BN];
    const int tid = threadIdx.x;
    const int m0 = blockIdx.y * BM, n0 = blockIdx.x * BN;
    const int lr = tid >> 1;
    const int lc = (tid & 1) * 4;
    const int tx = tid & 15, ty = tid >> 4;
    u64 acc[8][4];
#pragma unroll
    for (int i = 0; i < 8; i++)
#pragma unroll
        for (int j = 0; j < 4; j++) acc[i][j] = 0ull;

    {
        float4 av = *(const float4*)&A [(size_t)(m0 + lr) * NI + lc];
        float4 bv = *(const float4*)&Bm[(size_t)(n0 + lr) * NI + lc];
        As[0][lc + 0][lr] = av.x; As[0][lc + 1][lr] = av.y;
        As[0][lc + 2][lr] = av.z; As[0][lc + 3][lr] = av.w;
        Bs[0][lc + 0][lr] = bv.x; Bs[0][lc + 1][lr] = bv.y;
        Bs[0][lc + 2][lr] = bv.z; Bs[0][lc + 3][lr] = bv.w;
    }
    __syncthreads();

    for (int kc = 0; kc < NCHUNK; kc++) {
        const int buf = kc & 1;
        float4 avn, bvn;
        if (kc + 1 < NCHUNK) {
            avn = *(const float4*)&A [(size_t)(m0 + lr) * NI + (kc + 1) * BK + lc];
            bvn = *(const float4*)&Bm[(size_t)(n0 + lr) * NI + (kc + 1) * BK + lc];
        }
#pragma unroll
        for (int k = 0; k < BK; k++) {
            float4 a0 = *(const float4*)&As[buf][k][ty * 8];
            float4 a1 = *(const float4*)&As[buf][k][ty * 8 + 4];
            ulonglong2 bp = *(const ulonglong2*)&Bs[buf][k][tx * 8];
            ulonglong2 bq = *(const ulonglong2*)&Bs[buf][k][tx * 8 + 4];
            float aa[8] = {a0.x, a0.y, a0.z, a0.w, a1.x, a1.y, a1.z, a1.w};
            u64 ap[8];
#pragma unroll
            for (int i = 0; i < 8; i++) {
                u32 ab = __float_as_uint(aa[i]);
                PACK2(ap[i], ab, ab);
            }
#pragma unroll
            for (int i = 0; i < 8; i++) {
                FMA2(acc[i][0], ap[i], bp.x);
                FMA2(acc[i][1], ap[i], bp.y);
                FMA2(acc[i][2], ap[i], bq.x);
                FMA2(acc[i][3], ap[i], bq.y);
            }
        }
        if (kc + 1 < NCHUNK) {
            const int nb = buf ^ 1;
            As[nb][lc + 0][lr] = avn.x; As[nb][lc + 1][lr] = avn.y;
            As[nb][lc + 2][lr] = avn.z; As[nb][lc + 3][lr] = avn.w;
            Bs[nb][lc + 0][lr] = bvn.x; Bs[nb][lc + 1][lr] = bvn.y;
            Bs[nb][lc + 2][lr] = bvn.z; Bs[nb][lc + 3][lr] = bvn.w;
            __syncthreads();
        }
    }
#pragma unroll
    for (int i = 0; i < 8; i++) {
        float o[8];
#pragma unroll
        for (int j = 0; j < 4; j++) {
            u32 lo, hi;
            UNPK2(lo, hi, acc[i][j]);
            o[2 * j]     = __uint_as_float(lo);
            o[2 * j + 1] = __uint_as_float(hi);
        }
        float4 o0 = {o[0], o[1], o[2], o[3]};
        float4 o1 = {o[4], o[5], o[6], o[7]};
        float* dst = &g_Iext[(size_t)(m0 + ty * 8 + i) * NH + n0 + tx * 8];
        *(float4*)dst = o0;
        *(float4*)(dst + 4) = o1;
    }
}

#define RSTAGE(M, NHALF)                                                        \
    if (ln & (M)) {                                                             \
        _Pragma("unroll")                                                       \
        for (int i = 0; i < (NHALF); i++) {                                     \
            float tmp = a[i]; a[i] = a[i + (NHALF)]; a[i + (NHALF)] = tmp;      \
        }                                                                       \
    }                                                                           \
    _Pragma("unroll")                                                           \
    for (int i = 0; i < (NHALF); i++)                                           \
        a[i] += __shfl_xor_sync(0xffffffffu, a[i + (NHALF)], (M));

// -------- Phase B: persistent scan, 4 independent group barriers --------
// CTA c: group g = c>>6 (batches [8g, 8g+8)), cg = c&63, h slice
// [16cg, 16cg+16). Warp w owns h rows [16cg+4w, +4); all warps share the
// group's 8 batches. Lane math identical to R15: output ln = bb*4+hh.
__global__ __launch_bounds__(128, 2) void scan_kernel(const float* __restrict__ Wrec) {
    extern __shared__ float wt[];      // 16 rows x NH = 64 KB

    const int tid = threadIdx.x;
    const int w  = tid >> 5;
    const int ln = tid & 31;
    const int c  = blockIdx.x;
    const int g  = c >> 6;             // batch group
    const int cg = c & 63;
    const int h0 = cg * 16;

    // preload 16 weight rows: 4096 float4 over 128 threads
    {
        const float4* src = (const float4*)(Wrec + (size_t)h0 * NH);
#pragma unroll
        for (int i = 0; i < 32; i++)
            ((float4*)wt)[tid + i * 128] = src[tid + i * 128];
    }
    __syncthreads();

    const int b = 8 * g + (ln >> 2);
    const int h = h0 + 4 * w + (ln & 3);
    const float* wbase = wt + (4 * w) * NH + 4 * ln;
    unsigned int* bar = &g_bars[g][0];

    float v = V_RST, a0 = 0.f, a1 = 0.f, ref = 0.f, hs = 0.f, psc = 0.f;
    int cnt = 0;
    float Iv = __ldcg(&g_Iext[(size_t)b * NH + h]);

    for (int t = 0; t < T_STEPS; t++) {
        if (t > 0) {
            const float* sp = g_spkf[(t - 1) & 1];
            u64 acc[32];
#pragma unroll
            for (int i = 0; i < 32; i++) acc[i] = 0ull;

            ulonglong2 s[8], sn[8];
#pragma unroll
            for (int bb = 0; bb < 8; bb++)
                s[bb] = __ldcg((const ulonglong2*)(sp + (8 * g + bb) * NH + 4 * ln));

#pragma unroll
            for (int u = 0; u < 8; u++) {
                if (u < 7) {
#pragma unroll
                    for (int bb = 0; bb < 8; bb++)
                        sn[bb] = __ldcg((const ulonglong2*)(sp + (8 * g + bb) * NH
                                                               + 4 * ln + 128 * (u + 1)));
                }
#pragma unroll
                for (int hh = 0; hh < 4; hh++) {
                    ulonglong2 wv = *(const ulonglong2*)(wbase + hh * NH + 128 * u);
#pragma unroll
                    for (int bb = 0; bb < 8; bb++) {
                        FMA2(acc[bb * 4 + hh], s[bb].x, wv.x);
                        FMA2(acc[bb * 4 + hh], s[bb].y, wv.y);
                    }
                }
#pragma unroll
                for (int bb = 0; bb < 8; bb++) s[bb] = sn[bb];
            }

            float a[32];
#pragma unroll
            for (int i = 0; i < 32; i++) {
                u32 lo, hi;
                UNPK2(lo, hi, acc[i]);
                a[i] = __uint_as_float(lo) + __uint_as_float(hi);
            }
            RSTAGE(16, 16)
            RSTAGE(8, 8)
            RSTAGE(4, 4)
            RSTAGE(2, 2)
            RSTAGE(1, 1)
            float rec = a[0];

            hs  = D_SYN * hs + rec;
            psc = D_SYN * psc + hs;
        }

        float I = Iv + psc;
        a0 *= D_A0;
        a1 *= D_A1;
        v = v + ((V_RST - v) * (1.0f / 20.0f) + (I + a0 + a1) * 0.5f);
        bool in_ref = ref > 0.0f;
        if (in_ref) v = V_RST;
        float spike = (!in_ref && v >= V_TH) ? 1.0f : 0.0f;
        if (spike > 0.0f) {
            v = V_RST; a0 += 1.0f; a1 -= 2.0f; ref = 2.0f; cnt++;
        } else {
            ref = fmaxf(ref - 1.0f, 0.0f);
        }
        g_spkf[t & 1][b * NH + h] = spike;

        int tn = (t < T_STEPS - 1) ? t + 1 : t;
        Iv = __ldcg(&g_Iext[((size_t)tn * BATCH + b) * NH + h]);

        // group barrier: only this group's 64 CTAs participate
        __syncthreads();
        if (tid == 0) {
            asm volatile("red.release.gpu.global.add.u32 [%0], 1;"
                         :: "l"(bar) : "memory");
            const unsigned target = (unsigned)(t + 1) * GCTAS;
            unsigned cur;
            do {
                asm volatile("ld.global.acquire.gpu.u32 %0, [%1];"
                             : "=r"(cur) : "l"(bar));
            } while (cur < target);
        }
        __syncthreads();
    }
    g_rate[b * NH + h] = (float)cnt * 0.001f;
}

// -------- Phase C --------
__global__ __launch_bounds__(256) void out_kernel(const float* __restrict__ Wout,
                                                  float* __restrict__ out) {
    int gw   = (blockIdx.x * blockDim.x + threadIdx.x) >> 5;
    int lane = threadIdx.x & 31;
    int b = gw >> 8;
    int o = gw & 255;
    const float* r = &g_rate[b * NH];
    const float* wp = &Wout[(size_t)o * NH];
    float s = 0.f;
    for (int hh = lane; hh < NH; hh += 32) s += r[hh] * wp[hh];
#pragma unroll
    for (int off = 16; off; off >>= 1) s += __shfl_down_sync(0xffffffffu, s, off);
    if (lane == 0) out[b * NO + o] = s;
}

// -------- launch --------
extern "C" void kernel_launch(void* const* d_in, const int* in_sizes, int n_in,
                              void* d_out, int out_size) {
    const float* x = nullptr;
    const float* W_in = nullptr;
    const float* W_rec = nullptr;
    const float* W_out = nullptr;
    for (int i = 0; i < n_in; i++) {
        switch (in_sizes[i]) {
            case T_STEPS * BATCH * NI: x     = (const float*)d_in[i]; break;
            case NH * NI:              W_in  = (const float*)d_in[i]; break;
            case NH * NH:              W_rec = (const float*)d_in[i]; break;
            case NO * NH:              W_out = (const float*)d_in[i]; break;
        }
    }
    float* out = (float*)d_out;

    cudaFuncSetAttribute(scan_kernel,
                         cudaFuncAttributeMaxDynamicSharedMemorySize, 16 * NH * 4);

    // harness poisons occupy global idx 0,1
    init_kernel<<<1, 32>>>();                    // global 2

    dim3 g1(NH / BN, (T_STEPS * BATCH) / BM);    // (8, 250)
    gemm_in_kernel<<<g1, 256>>>(x, W_in);        // global 3

    init_kernel<<<1, 32>>>();                    // global 4 (idempotent)

    scan_kernel<<<NBLK, 128, 16 * NH * 4>>>(W_rec);  // global 5 <- ncu -s 5

    out_kernel<<<(BATCH * NO * 32) / 256, 256>>>(W_out, out);   // global 6
}